// round 1
// baseline (speedup 1.0000x reference)
#include <cuda_runtime.h>

// Fused RBF attention, fp32 baseline.
//   out  = ((attn/rowsum) @ v) @ Wo + bo    [B,Q,H]
//   attn = exp(-(|q|^2+|k|^2-2 q.k)/8) / rowsum   [B,Q,K]
// Output buffer layout assumed: out (B*Q*H floats) followed by attn (B*Q*K floats),
// with defensive handling if out_size indicates only one of them.

#define BATCH 4
#define SEQ   2048
#define DIN   128
#define HDIM  64
#define KBLK  16                 // SEQ / 128 k-tiles
#define ROWS  (BATCH*SEQ)        // 8192 total rows

// ---- device scratch (no allocations allowed) ----
__device__ float g_q[ROWS*HDIM];
__device__ float g_k[ROWS*HDIM];
__device__ float g_v[ROWS*HDIM];
__device__ float g_q2[ROWS];
__device__ float g_k2[ROWS];
__device__ float g_rsump[KBLK][ROWS];      // per-kblock rowsum partials (deterministic, no atomics)
__device__ float g_rinv[ROWS];
__device__ float g_ctxp[KBLK][ROWS*HDIM];  // per-kblock ctx partials (unnormalized)
__device__ float g_outs[ROWS*HDIM];        // fallback out scratch

// ================= projections: y = X @ W + b, plus rownorm^2 =================
__global__ __launch_bounds__(256) void k_proj(
    const float* __restrict__ qs, const float* __restrict__ ks, const float* __restrict__ vs,
    const float* __restrict__ Wq, const float* __restrict__ bq,
    const float* __restrict__ Wk, const float* __restrict__ bk,
    const float* __restrict__ Wv, const float* __restrict__ bv)
{
    const float* X; const float* W; const float* bias; float* Y; float* sq;
    switch (blockIdx.y) {
        case 0:  X = qs; W = Wq; bias = bq; Y = g_q; sq = g_q2; break;
        case 1:  X = ks; W = Wk; bias = bk; Y = g_k; sq = g_k2; break;
        default: X = vs; W = Wv; bias = bv; Y = g_v; sq = nullptr; break;
    }
    __shared__ float Xs[32][132];   // X tile transposed [d][row], pad for banks
    __shared__ float Ws[32][68];    // W tile natural [d][h]

    int tid = threadIdx.x;
    int hg = tid & 7;        // 8 h-groups (8 cols each)
    int rg = tid >> 3;       // 32 row-groups (4 rows each)
    int row0 = blockIdx.x * 128;

    float acc[4][8];
    #pragma unroll
    for (int i = 0; i < 4; i++)
        #pragma unroll
        for (int j = 0; j < 8; j++) acc[i][j] = 0.f;

    for (int d0 = 0; d0 < DIN; d0 += 32) {
        #pragma unroll
        for (int it = 0; it < 4; it++) {               // 128 rows x 32 d = 1024 float4
            int f4 = it * 256 + tid;
            int r = f4 >> 3, d4 = (f4 & 7) * 4;
            float4 x = *(const float4*)&X[(row0 + r) * DIN + d0 + d4];
            Xs[d4 + 0][r] = x.x; Xs[d4 + 1][r] = x.y;
            Xs[d4 + 2][r] = x.z; Xs[d4 + 3][r] = x.w;
        }
        #pragma unroll
        for (int it = 0; it < 2; it++) {               // 32 d x 64 h = 512 float4
            int f4 = it * 256 + tid;
            int dk = f4 >> 4, h4 = (f4 & 15) * 4;
            *(float4*)&Ws[dk][h4] = *(const float4*)&W[(d0 + dk) * HDIM + h4];
        }
        __syncthreads();
        #pragma unroll
        for (int dk = 0; dk < 32; dk++) {
            float4 xa = *(float4*)&Xs[dk][rg * 4];
            float4 w0 = *(float4*)&Ws[dk][hg * 8];
            float4 w1 = *(float4*)&Ws[dk][hg * 8 + 4];
            float xf[4] = {xa.x, xa.y, xa.z, xa.w};
            float wf[8] = {w0.x, w0.y, w0.z, w0.w, w1.x, w1.y, w1.z, w1.w};
            #pragma unroll
            for (int i = 0; i < 4; i++)
                #pragma unroll
                for (int j = 0; j < 8; j++) acc[i][j] += xf[i] * wf[j];
        }
        __syncthreads();
    }

    float bb[8];
    #pragma unroll
    for (int j = 0; j < 8; j++) bb[j] = bias[hg * 8 + j];

    #pragma unroll
    for (int i = 0; i < 4; i++) {
        int row = row0 + rg * 4 + i;
        float y[8]; float p = 0.f;
        #pragma unroll
        for (int j = 0; j < 8; j++) { y[j] = acc[i][j] + bb[j]; p += y[j] * y[j]; }
        *(float4*)&Y[row * HDIM + hg * 8]     = make_float4(y[0], y[1], y[2], y[3]);
        *(float4*)&Y[row * HDIM + hg * 8 + 4] = make_float4(y[4], y[5], y[6], y[7]);
        // reduce |y|^2 across the 8 h-group lanes (consecutive lanes)
        p += __shfl_xor_sync(0xffffffffu, p, 4);
        p += __shfl_xor_sync(0xffffffffu, p, 2);
        p += __shfl_xor_sync(0xffffffffu, p, 1);
        if (sq && hg == 0) sq[row] = p;
    }
}

// ======== fused scores (exp) + unnormalized attn write + ctx partial ==========
// smem budget: Qs[64][132] + Ks[64][132] (aliased later by St[128][132]) + Vs[128][68]
#define SM_QK (64 * 132)
#define SM_VS (128 * 68)
#define SMEM_BYTES ((2 * SM_QK + SM_VS) * 4)   // 102400 bytes

__global__ __launch_bounds__(256, 2) void k_attn(float* __restrict__ attn, int do_attn)
{
    extern __shared__ float smem[];
    float* Qs = smem;              // [64][132]  (h-major, transposed)
    float* Ks = smem + SM_QK;      // [64][132]
    float* St = smem;              // [128][132] alias over Qs+Ks (score tile, k-major)
    float* Vs = smem + 2 * SM_QK;  // [128][68]

    int tid = threadIdx.x;
    int kb = blockIdx.x, qb = blockIdx.y, b = blockIdx.z;
    int q0 = b * SEQ + qb * 128;   // global row base for q
    int k0 = b * SEQ + kb * 128;   // global row base for k/v

    // ---- stage q,k transposed; v natural ----
    #pragma unroll
    for (int it = 0; it < 8; it++) {
        int f4 = it * 256 + tid;               // 2048 float4 per tile
        int r = f4 >> 4, h4 = (f4 & 15) * 4;
        float4 qv = *(const float4*)&g_q[(q0 + r) * HDIM + h4];
        Qs[(h4 + 0) * 132 + r] = qv.x; Qs[(h4 + 1) * 132 + r] = qv.y;
        Qs[(h4 + 2) * 132 + r] = qv.z; Qs[(h4 + 3) * 132 + r] = qv.w;
        float4 kv = *(const float4*)&g_k[(k0 + r) * HDIM + h4];
        Ks[(h4 + 0) * 132 + r] = kv.x; Ks[(h4 + 1) * 132 + r] = kv.y;
        Ks[(h4 + 2) * 132 + r] = kv.z; Ks[(h4 + 3) * 132 + r] = kv.w;
        float4 vv = *(const float4*)&g_v[(k0 + r) * HDIM + h4];
        *(float4*)&Vs[r * 68 + h4] = vv;
    }
    __syncthreads();

    // ---- score GEMM: 8x8 per thread, inner dim 64 ----
    int tx = tid & 15, ty = tid >> 4;
    float acc[8][8];
    #pragma unroll
    for (int i = 0; i < 8; i++)
        #pragma unroll
        for (int j = 0; j < 8; j++) acc[i][j] = 0.f;

    #pragma unroll 8
    for (int h = 0; h < 64; h++) {
        float4 qa = *(float4*)&Qs[h * 132 + ty * 8];
        float4 qc = *(float4*)&Qs[h * 132 + ty * 8 + 4];
        float4 ka = *(float4*)&Ks[h * 132 + tx * 8];
        float4 kc = *(float4*)&Ks[h * 132 + tx * 8 + 4];
        float qf[8] = {qa.x, qa.y, qa.z, qa.w, qc.x, qc.y, qc.z, qc.w};
        float kf[8] = {ka.x, ka.y, ka.z, ka.w, kc.x, kc.y, kc.z, kc.w};
        #pragma unroll
        for (int i = 0; i < 8; i++)
            #pragma unroll
            for (int j = 0; j < 8; j++) acc[i][j] += qf[i] * kf[j];
    }

    float q2v[8], k2v[8];
    #pragma unroll
    for (int i = 0; i < 8; i++) q2v[i] = g_q2[q0 + ty * 8 + i];
    #pragma unroll
    for (int j = 0; j < 8; j++) k2v[j] = g_k2[k0 + tx * 8 + j];

    // ---- exp, rowsum partial, unnormalized attn write ----
    #pragma unroll
    for (int i = 0; i < 8; i++) {
        float rs = 0.f;
        #pragma unroll
        for (int j = 0; j < 8; j++) {
            float d = q2v[i] + k2v[j] - 2.f * acc[i][j];
            float e = __expf(-0.125f * d);   // exp(-d_sq / sqrt(64))
            acc[i][j] = e;
            rs += e;
        }
        rs += __shfl_xor_sync(0xffffffffu, rs, 8);
        rs += __shfl_xor_sync(0xffffffffu, rs, 4);
        rs += __shfl_xor_sync(0xffffffffu, rs, 2);
        rs += __shfl_xor_sync(0xffffffffu, rs, 1);
        if (tx == 0) g_rsump[kb][q0 + ty * 8 + i] = rs;
        if (do_attn) {
            int arow = (q0 + ty * 8 + i) * SEQ + (kb * 128 + tx * 8);
            *(float4*)&attn[arow]     = make_float4(acc[i][0], acc[i][1], acc[i][2], acc[i][3]);
            *(float4*)&attn[arow + 4] = make_float4(acc[i][4], acc[i][5], acc[i][6], acc[i][7]);
        }
    }

    // ---- transpose score tile into smem (aliases dead Qs/Ks) ----
    __syncthreads();
    #pragma unroll
    for (int i = 0; i < 8; i++)
        #pragma unroll
        for (int j = 0; j < 8; j++)
            St[(tx * 8 + j) * 132 + (ty * 8 + i)] = acc[i][j];
    __syncthreads();

    // ---- ctx partial: [128 m][64 h] += St^T @ V, 4x8 per thread ----
    int hg = tid & 7, rg = tid >> 3;
    float ca[4][8];
    #pragma unroll
    for (int i = 0; i < 4; i++)
        #pragma unroll
        for (int j = 0; j < 8; j++) ca[i][j] = 0.f;

    #pragma unroll 8
    for (int kk = 0; kk < 128; kk++) {
        float4 a  = *(float4*)&St[kk * 132 + rg * 4];
        float4 v0 = *(float4*)&Vs[kk * 68 + hg * 8];
        float4 v1 = *(float4*)&Vs[kk * 68 + hg * 8 + 4];
        float af[4] = {a.x, a.y, a.z, a.w};
        float vf[8] = {v0.x, v0.y, v0.z, v0.w, v1.x, v1.y, v1.z, v1.w};
        #pragma unroll
        for (int i = 0; i < 4; i++)
            #pragma unroll
            for (int j = 0; j < 8; j++) ca[i][j] += af[i] * vf[j];
    }
    #pragma unroll
    for (int i = 0; i < 4; i++) {
        int row = q0 + rg * 4 + i;
        *(float4*)&g_ctxp[kb][row * HDIM + hg * 8]     = make_float4(ca[i][0], ca[i][1], ca[i][2], ca[i][3]);
        *(float4*)&g_ctxp[kb][row * HDIM + hg * 8 + 4] = make_float4(ca[i][4], ca[i][5], ca[i][6], ca[i][7]);
    }
}

// ============== reduce rowsum partials -> reciprocal ==============
__global__ void k_rinv()
{
    int i = blockIdx.x * blockDim.x + threadIdx.x;
    if (i < ROWS) {
        float s = 0.f;
        #pragma unroll
        for (int p = 0; p < KBLK; p++) s += g_rsump[p][i];
        g_rinv[i] = 1.0f / s;
    }
}

// ============== normalize attn in place ==============
__global__ void k_norm(float* __restrict__ attn)
{
    int i4 = blockIdx.x * blockDim.x + threadIdx.x;   // ATTN/4 threads total
    int e = i4 * 4;
    float r = g_rinv[e >> 11];                        // row = e / 2048 (4 elems share a row)
    float4 a = *(float4*)&attn[e];
    a.x *= r; a.y *= r; a.z *= r; a.w *= r;
    *(float4*)&attn[e] = a;
}

// ============== out = (sum ctx partials * rinv) @ Wo + bo ==============
__global__ __launch_bounds__(256) void k_out(
    const float* __restrict__ Wo, const float* __restrict__ bo, float* __restrict__ out)
{
    __shared__ float cs[4][64];
    int tid = threadIdx.x;
    int r = tid >> 6, h = tid & 63;
    int row = blockIdx.x * 4 + r;
    float c = 0.f;
    #pragma unroll
    for (int p = 0; p < KBLK; p++) c += g_ctxp[p][row * HDIM + h];
    c *= g_rinv[row];
    cs[r][h] = c;
    __syncthreads();
    float o = bo[h];
    #pragma unroll 16
    for (int hp = 0; hp < HDIM; hp++) o += cs[r][hp] * Wo[hp * HDIM + h];
    out[row * HDIM + h] = o;
}

// =========================== launch ===========================
extern "C" void kernel_launch(void* const* d_in, const int* in_sizes, int n_in,
                              void* d_out, int out_size)
{
    const float* qs = (const float*)d_in[0];
    const float* ks = (const float*)d_in[1];
    const float* vs = (const float*)d_in[2];
    const float* Wq = (const float*)d_in[3];
    const float* bq = (const float*)d_in[4];
    const float* Wk = (const float*)d_in[5];
    const float* bk = (const float*)d_in[6];
    const float* Wv = (const float*)d_in[7];
    const float* bv = (const float*)d_in[8];
    const float* Wo = (const float*)d_in[9];
    const float* bo = (const float*)d_in[10];

    const int OUTN = ROWS * HDIM;          // 524288
    const int ATTN = ROWS * SEQ;           // 16777216

    float* souts = nullptr;
    cudaGetSymbolAddress((void**)&souts, g_outs);

    float* outp; float* attnp;
    if (out_size >= OUTN + ATTN)      { outp = (float*)d_out; attnp = (float*)d_out + OUTN; }
    else if (out_size == ATTN)        { outp = souts;         attnp = (float*)d_out; }
    else                              { outp = (float*)d_out; attnp = nullptr; }

    cudaFuncSetAttribute(k_attn, cudaFuncAttributeMaxDynamicSharedMemorySize, SMEM_BYTES);

    k_proj<<<dim3(ROWS / 128, 3), 256>>>(qs, ks, vs, Wq, bq, Wk, bk, Wv, bv);
    k_attn<<<dim3(KBLK, SEQ / 128, BATCH), 256, SMEM_BYTES>>>(
        attnp ? attnp : (float*)d_out, attnp != nullptr ? 1 : 0);
    k_rinv<<<(ROWS + 255) / 256, 256>>>();
    if (attnp) k_norm<<<(ATTN / 4) / 256, 256>>>(attnp);
    k_out<<<ROWS / 4, 256>>>(Wo, bo, outp);
}

// round 3
// speedup vs baseline: 1.5303x; 1.5303x over previous
#include <cuda_runtime.h>
#include <cstdint>

#define BATCH 4
#define SEQ   2048
#define DIN   128
#define HDIM  64
#define ROWS  (BATCH*SEQ)        // 8192
#define TQ    64                 // q rows per block in k_attn2
#define KT    128                // k cols per tile
#define NKB   (SEQ/KT)           // 16

// ---- device scratch (no allocations allowed) ----
__device__ float g_q [ROWS*HDIM];
__device__ float g_kT[BATCH*HDIM*SEQ];   // k projected, transposed: [b][h][s]
__device__ float g_v [ROWS*HDIM];
__device__ float g_q2[ROWS];
__device__ float g_k2[ROWS];
__device__ float g_ctx[ROWS*HDIM];       // normalized ctx
__device__ float g_outs[ROWS*HDIM];      // fallback out scratch

// ================= cp.async helpers =================
__device__ __forceinline__ void cpa16(void* dst_smem, const void* src) {
    unsigned d = (unsigned)__cvta_generic_to_shared(dst_smem);
    asm volatile("cp.async.cg.shared.global [%0], [%1], 16;\n" :: "r"(d), "l"(src));
}
#define CP_COMMIT() asm volatile("cp.async.commit_group;\n")
#define CP_WAIT(N)  asm volatile("cp.async.wait_group %0;\n" :: "n"(N))

// ================= tf32 mma =================
__device__ __forceinline__ void mma_tf32(float& d0, float& d1, float& d2, float& d3,
                                         float a0, float a1, float a2, float a3,
                                         float b0, float b1)
{
    asm volatile(
        "mma.sync.aligned.m16n8k8.row.col.f32.tf32.tf32.f32 "
        "{%0,%1,%2,%3}, {%4,%5,%6,%7}, {%8,%9}, {%0,%1,%2,%3};\n"
        : "+f"(d0), "+f"(d1), "+f"(d2), "+f"(d3)
        : "r"(__float_as_uint(a0)), "r"(__float_as_uint(a1)),
          "r"(__float_as_uint(a2)), "r"(__float_as_uint(a3)),
          "r"(__float_as_uint(b0)), "r"(__float_as_uint(b1)));
}

// ================= projections: y = X @ W + b, plus rownorm^2 =================
__global__ __launch_bounds__(256) void k_proj(
    const float* __restrict__ qs, const float* __restrict__ ks, const float* __restrict__ vs,
    const float* __restrict__ Wq, const float* __restrict__ bq,
    const float* __restrict__ Wk, const float* __restrict__ bk,
    const float* __restrict__ Wv, const float* __restrict__ bv)
{
    const float* X; const float* W; const float* bias; float* Y; float* sq;
    int mode = blockIdx.y;
    switch (mode) {
        case 0:  X = qs; W = Wq; bias = bq; Y = g_q;  sq = g_q2; break;
        case 1:  X = ks; W = Wk; bias = bk; Y = nullptr; sq = g_k2; break;
        default: X = vs; W = Wv; bias = bv; Y = g_v;  sq = nullptr; break;
    }
    __shared__ float Xs[32][132];
    __shared__ float Ws[32][68];

    int tid = threadIdx.x;
    int hg = tid & 7;
    int rg = tid >> 3;
    int row0 = blockIdx.x * 128;

    float acc[4][8];
    #pragma unroll
    for (int i = 0; i < 4; i++)
        #pragma unroll
        for (int j = 0; j < 8; j++) acc[i][j] = 0.f;

    for (int d0 = 0; d0 < DIN; d0 += 32) {
        #pragma unroll
        for (int it = 0; it < 4; it++) {
            int f4 = it * 256 + tid;
            int r = f4 >> 3, d4 = (f4 & 7) * 4;
            float4 x = *(const float4*)&X[(row0 + r) * DIN + d0 + d4];
            Xs[d4 + 0][r] = x.x; Xs[d4 + 1][r] = x.y;
            Xs[d4 + 2][r] = x.z; Xs[d4 + 3][r] = x.w;
        }
        #pragma unroll
        for (int it = 0; it < 2; it++) {
            int f4 = it * 256 + tid;
            int dk = f4 >> 4, h4 = (f4 & 15) * 4;
            *(float4*)&Ws[dk][h4] = *(const float4*)&W[(d0 + dk) * HDIM + h4];
        }
        __syncthreads();
        #pragma unroll
        for (int dk = 0; dk < 32; dk++) {
            float4 xa = *(float4*)&Xs[dk][rg * 4];
            float4 w0 = *(float4*)&Ws[dk][hg * 8];
            float4 w1 = *(float4*)&Ws[dk][hg * 8 + 4];
            float xf[4] = {xa.x, xa.y, xa.z, xa.w};
            float wf[8] = {w0.x, w0.y, w0.z, w0.w, w1.x, w1.y, w1.z, w1.w};
            #pragma unroll
            for (int i = 0; i < 4; i++)
                #pragma unroll
                for (int j = 0; j < 8; j++) acc[i][j] += xf[i] * wf[j];
        }
        __syncthreads();
    }

    float bb[8];
    #pragma unroll
    for (int j = 0; j < 8; j++) bb[j] = bias[hg * 8 + j];

    #pragma unroll
    for (int i = 0; i < 4; i++) {
        int row = row0 + rg * 4 + i;
        float y[8]; float p = 0.f;
        #pragma unroll
        for (int j = 0; j < 8; j++) { y[j] = acc[i][j] + bb[j]; p += y[j] * y[j]; }
        if (mode == 1) {
            int b = row >> 11;            // / SEQ
            int s = row & (SEQ - 1);
            #pragma unroll
            for (int j = 0; j < 8; j++)
                g_kT[((size_t)b * HDIM + hg * 8 + j) * SEQ + s] = y[j];
        } else {
            *(float4*)&Y[row * HDIM + hg * 8]     = make_float4(y[0], y[1], y[2], y[3]);
            *(float4*)&Y[row * HDIM + hg * 8 + 4] = make_float4(y[4], y[5], y[6], y[7]);
        }
        p += __shfl_xor_sync(0xffffffffu, p, 4);
        p += __shfl_xor_sync(0xffffffffu, p, 2);
        p += __shfl_xor_sync(0xffffffffu, p, 1);
        if (sq && hg == 0) sq[row] = p;
    }
}

// ======== fused attention: per 64-q-row block over all 2048 k ==========
// smem floats: Qs 64x68, Ks[2] 64x136, Vs[2] 128x72, k2s[2] 128, Ss 64x132, red 192
#define OFF_QS   0
#define OFF_KS0  (OFF_QS  + 64*68)
#define OFF_KS1  (OFF_KS0 + 64*136)
#define OFF_VS0  (OFF_KS1 + 64*136)
#define OFF_VS1  (OFF_VS0 + 128*72)
#define OFF_K20  (OFF_VS1 + 128*72)
#define OFF_K21  (OFF_K20 + 128)
#define OFF_SS   (OFF_K21 + 128)
#define OFF_RED  (OFF_SS  + 64*132)
#define SMEM_FLOATS (OFF_RED + 192)
#define SMEM_BYTES  (SMEM_FLOATS * 4)   // 196352

__global__ __launch_bounds__(256, 1) void k_attn2(float* __restrict__ attn, int do_attn)
{
    extern __shared__ float sm[];
    float* Qs  = sm + OFF_QS;
    float* KsB[2] = { sm + OFF_KS0, sm + OFF_KS1 };
    float* VsB[2] = { sm + OFF_VS0, sm + OFF_VS1 };
    float* k2B[2] = { sm + OFF_K20, sm + OFF_K21 };
    float* Ss  = sm + OFF_SS;
    float* red = sm + OFF_RED;           // [0..127] partials, [128..191] rinv
    float* rinv = red + 128;

    const int tid  = threadIdx.x;
    const int lane = tid & 31;
    const int wid  = tid >> 5;
    const int g    = lane >> 2;          // groupID
    const int tig  = lane & 3;           // threadID in group
    const int wm   = wid & 3;            // warp m-tile (16 rows each -> 64)
    const int wn   = wid >> 2;           // warp n-half (0/1)

    const int row0 = blockIdx.x * TQ;    // global q row base
    const int b    = row0 >> 11;         // batch
    const float* kT_base = g_kT + (size_t)b * HDIM * SEQ;
    const float* v_base  = g_v  + (size_t)b * SEQ * HDIM;
    const float* k2_base = g_k2 + b * SEQ;

    // ---- prologue: stage Q + K/V tile 0 via cp.async ----
    // Q: 64 rows x 64 floats = 1024 x 16B -> 4 ops/thread
    #pragma unroll
    for (int it = 0; it < 4; it++) {
        int op = it * 256 + tid;            // 0..1023
        int r = op >> 4, c = (op & 15) * 4; // 16 x float4 per row
        cpa16(&Qs[r * 68 + c], &g_q[(size_t)(row0 + r) * HDIM + c]);
    }
    // K tile 0: 64 h-rows x 128 floats = 2048 x 16B
    #pragma unroll
    for (int it = 0; it < 8; it++) {
        int op = it * 256 + tid;            // 0..2047
        int h = op >> 5, c = (op & 31) * 4; // 32 x float4 per row
        cpa16(&KsB[0][h * 136 + c], kT_base + (size_t)h * SEQ + c);
    }
    // V tile 0: 128 rows x 64 floats = 2048 x 16B
    #pragma unroll
    for (int it = 0; it < 8; it++) {
        int op = it * 256 + tid;
        int r = op >> 4, c = (op & 15) * 4; // 16 x float4 per row
        cpa16(&VsB[0][r * 72 + c], v_base + (size_t)r * HDIM + c);
    }
    if (tid < 32) cpa16(&k2B[0][tid * 4], k2_base + tid * 4);
    CP_COMMIT();

    // ---- per-thread persistent state ----
    float q2r0 = g_q2[row0 + wm * 16 + g];
    float q2r1 = g_q2[row0 + wm * 16 + g + 8];
    float rs0 = 0.f, rs1 = 0.f;
    float cacc[4][4];
    #pragma unroll
    for (int i = 0; i < 4; i++)
        #pragma unroll
        for (int j = 0; j < 4; j++) cacc[i][j] = 0.f;

    for (int kb = 0; kb < NKB; kb++) {
        const int bf = kb & 1;
        // prefetch next tile
        if (kb + 1 < NKB) {
            const int nb = (kb + 1) & 1;
            const float* kTn = kT_base + (kb + 1) * KT;
            const float* vn  = v_base + (size_t)(kb + 1) * KT * HDIM;
            #pragma unroll
            for (int it = 0; it < 8; it++) {
                int op = it * 256 + tid;
                int h = op >> 5, c = (op & 31) * 4;
                cpa16(&KsB[nb][h * 136 + c], kTn + (size_t)h * SEQ + c);
            }
            #pragma unroll
            for (int it = 0; it < 8; it++) {
                int op = it * 256 + tid;
                int r = op >> 4, c = (op & 15) * 4;
                cpa16(&VsB[nb][r * 72 + c], vn + (size_t)r * HDIM + c);
            }
            if (tid < 32) cpa16(&k2B[nb][tid * 4], k2_base + (kb + 1) * KT + tid * 4);
            CP_COMMIT();
            CP_WAIT(1);
        } else {
            CP_WAIT(0);
        }
        __syncthreads();

        float* Ks = KsB[bf];
        float* Vs = VsB[bf];
        float* k2s = k2B[bf];

        // ---- scores: 64q x 128k = warps 4(m) x 2(n), warp tile 16x64 ----
        float sacc[8][4];
        #pragma unroll
        for (int i = 0; i < 8; i++)
            #pragma unroll
            for (int j = 0; j < 4; j++) sacc[i][j] = 0.f;

        #pragma unroll
        for (int kk = 0; kk < 8; kk++) {
            int ar = (wm * 16 + g) * 68 + kk * 8 + tig;
            float a0 = Qs[ar];
            float a1 = Qs[ar + 8 * 68];
            float a2 = Qs[ar + 4];
            float a3 = Qs[ar + 8 * 68 + 4];
            #pragma unroll
            for (int nt = 0; nt < 8; nt++) {
                int n0 = wn * 64 + nt * 8;
                float b0 = Ks[(kk * 8 + tig) * 136 + n0 + g];
                float b1 = Ks[(kk * 8 + tig + 4) * 136 + n0 + g];
                mma_tf32(sacc[nt][0], sacc[nt][1], sacc[nt][2], sacc[nt][3],
                         a0, a1, a2, a3, b0, b1);
            }
        }

        // ---- exp + rowsum + store S to smem ----
        #pragma unroll
        for (int nt = 0; nt < 8; nt++) {
            int cg = wn * 64 + nt * 8 + 2 * tig;
            float2 k2p = *(float2*)&k2s[cg];
            float e00 = __expf(-0.125f * (q2r0 + k2p.x - 2.f * sacc[nt][0]));
            float e01 = __expf(-0.125f * (q2r0 + k2p.y - 2.f * sacc[nt][1]));
            float e10 = __expf(-0.125f * (q2r1 + k2p.x - 2.f * sacc[nt][2]));
            float e11 = __expf(-0.125f * (q2r1 + k2p.y - 2.f * sacc[nt][3]));
            rs0 += e00 + e01;
            rs1 += e10 + e11;
            int r = wm * 16 + g;
            *(float2*)&Ss[r * 132 + cg]       = make_float2(e00, e01);
            *(float2*)&Ss[(r + 8) * 132 + cg] = make_float2(e10, e11);
        }
        __syncthreads();

        // ---- write unnormalized attn tile (coalesced from Ss) ----
        if (do_attn) {
            #pragma unroll
            for (int it = 0; it < 8; it++) {
                int f = it * 256 + tid;           // 0..2047 float4
                int r = f >> 5, c4 = (f & 31) * 4;
                float4 v4 = *(float4*)&Ss[r * 132 + c4];
                *(float4*)&attn[(size_t)(row0 + r) * SEQ + kb * KT + c4] = v4;
            }
        }

        // ---- ctx accumulate: 64q x 64h, warp tile 16x32, k-dim 128 ----
        #pragma unroll
        for (int kk = 0; kk < 16; kk++) {
            int ar = (wm * 16 + g) * 132 + kk * 8 + tig;
            float a0 = Ss[ar];
            float a1 = Ss[ar + 8 * 132];
            float a2 = Ss[ar + 4];
            float a3 = Ss[ar + 8 * 132 + 4];
            #pragma unroll
            for (int nt = 0; nt < 4; nt++) {
                int n0 = wn * 32 + nt * 8;
                float b0 = Vs[(kk * 8 + tig) * 72 + n0 + g];
                float b1 = Vs[(kk * 8 + tig + 4) * 72 + n0 + g];
                mma_tf32(cacc[nt][0], cacc[nt][1], cacc[nt][2], cacc[nt][3],
                         a0, a1, a2, a3, b0, b1);
            }
        }
        __syncthreads();
    }

    // ---- rowsum reduce -> rinv ----
    rs0 += __shfl_xor_sync(0xffffffffu, rs0, 1);
    rs0 += __shfl_xor_sync(0xffffffffu, rs0, 2);
    rs1 += __shfl_xor_sync(0xffffffffu, rs1, 1);
    rs1 += __shfl_xor_sync(0xffffffffu, rs1, 2);
    if (tig == 0) {
        red[wn * 64 + wm * 16 + g]     = rs0;
        red[wn * 64 + wm * 16 + g + 8] = rs1;
    }
    __syncthreads();
    if (tid < 64) rinv[tid] = 1.0f / (red[tid] + red[64 + tid]);
    __syncthreads();

    // ---- write normalized ctx ----
    {
        float ri0 = rinv[wm * 16 + g];
        float ri1 = rinv[wm * 16 + g + 8];
        int r0_ = row0 + wm * 16 + g;
        #pragma unroll
        for (int nt = 0; nt < 4; nt++) {
            int col = wn * 32 + nt * 8 + 2 * tig;
            *(float2*)&g_ctx[(size_t)r0_ * HDIM + col] =
                make_float2(cacc[nt][0] * ri0, cacc[nt][1] * ri0);
            *(float2*)&g_ctx[(size_t)(r0_ + 8) * HDIM + col] =
                make_float2(cacc[nt][2] * ri1, cacc[nt][3] * ri1);
        }
    }

    // ---- normalize attn in place (tiles likely L2-resident) ----
    if (do_attn) {
        for (int kb = 0; kb < NKB; kb++) {
            #pragma unroll
            for (int it = 0; it < 8; it++) {
                int f = it * 256 + tid;
                int r = f >> 5, c4 = (f & 31) * 4;
                float ri = rinv[r];
                float* p = &attn[(size_t)(row0 + r) * SEQ + kb * KT + c4];
                float4 v4 = *(float4*)p;
                v4.x *= ri; v4.y *= ri; v4.z *= ri; v4.w *= ri;
                *(float4*)p = v4;
            }
        }
    }
}

// ============== out = ctx @ Wo + bo (ctx already normalized) ==============
__global__ __launch_bounds__(256) void k_out(
    const float* __restrict__ Wo, const float* __restrict__ bo, float* __restrict__ out)
{
    __shared__ float cs[4][64];
    int tid = threadIdx.x;
    int r = tid >> 6, h = tid & 63;
    int row = blockIdx.x * 4 + r;
    cs[r][h] = g_ctx[(size_t)row * HDIM + h];
    __syncthreads();
    float o = bo[h];
    #pragma unroll 16
    for (int hp = 0; hp < HDIM; hp++) o += cs[r][hp] * Wo[hp * HDIM + h];
    out[(size_t)row * HDIM + h] = o;
}

// =========================== launch ===========================
extern "C" void kernel_launch(void* const* d_in, const int* in_sizes, int n_in,
                              void* d_out, int out_size)
{
    const float* qs = (const float*)d_in[0];
    const float* ks = (const float*)d_in[1];
    const float* vs = (const float*)d_in[2];
    const float* Wq = (const float*)d_in[3];
    const float* bq = (const float*)d_in[4];
    const float* Wk = (const float*)d_in[5];
    const float* bk = (const float*)d_in[6];
    const float* Wv = (const float*)d_in[7];
    const float* bv = (const float*)d_in[8];
    const float* Wo = (const float*)d_in[9];
    const float* bo = (const float*)d_in[10];

    const int OUTN = ROWS * HDIM;        // 524288
    const int ATTN = ROWS * SEQ;         // 16777216

    float* souts = nullptr;
    cudaGetSymbolAddress((void**)&souts, g_outs);

    float* outp; float* attnp;
    if (out_size >= OUTN + ATTN)      { outp = (float*)d_out; attnp = (float*)d_out + OUTN; }
    else if (out_size == ATTN)        { outp = souts;         attnp = (float*)d_out; }
    else                              { outp = (float*)d_out; attnp = nullptr; }

    cudaFuncSetAttribute(k_attn2, cudaFuncAttributeMaxDynamicSharedMemorySize, SMEM_BYTES);

    k_proj<<<dim3(ROWS / 128, 3), 256>>>(qs, ks, vs, Wq, bq, Wk, bk, Wv, bv);
    k_attn2<<<ROWS / TQ, 256, SMEM_BYTES>>>(attnp ? attnp : (float*)d_out,
                                            attnp != nullptr ? 1 : 0);
    k_out<<<ROWS / 4, 256>>>(Wo, bo, outp);
}